// round 8
// baseline (speedup 1.0000x reference)
#include <cuda_runtime.h>
#include <cstdint>

// Problem constants (shapes are fixed by the dataset).
static constexpr int cN = 300000;
static constexpr int cE = 1500000;
static constexpr int cG = 30000;

// Scratch (device globals — no allocation allowed). Zero-initialized at load;
// the transform kernels re-zero agg1/agg2 each call to keep the invariant.
__device__ float g_x0[(size_t)cN * 32];
__device__ float g_h1[(size_t)cN * 64];
__device__ float g_h2[(size_t)cN * 64];
__device__ float g_agg1[(size_t)cN * 3 * 32];   // layer-1 aggregates [N][3][32]
__device__ float g_agg2[(size_t)cN * 3 * 64];   // layer-2 aggregates [N][3][64]
__device__ int   g_cnt[(size_t)cN * 3];
__device__ float g_inv[(size_t)cN * 3];
__device__ float g_gsum[(size_t)cG * 64];
__device__ int   g_gcnt[cG];

// ---------------------------------------------------------------------------
// Packed fp32x2 helpers (Blackwell FFMA2 path — only reachable via PTX).
__device__ __forceinline__ unsigned long long pack2(float x, float y) {
    unsigned long long r;
    asm("mov.b64 %0, {%1, %2};" : "=l"(r)
        : "r"(__float_as_uint(x)), "r"(__float_as_uint(y)));
    return r;
}
__device__ __forceinline__ void ffma2(unsigned long long& d,
                                      unsigned long long a, unsigned long long b) {
    asm("fma.rn.f32x2 %0, %1, %2, %0;" : "+l"(d) : "l"(a), "l"(b));
}
__device__ __forceinline__ void unpack2(unsigned long long v, float& lo, float& hi) {
    unsigned int a, b;
    asm("mov.b64 {%0, %1}, %2;" : "=r"(a), "=r"(b) : "l"(v));
    lo = __uint_as_float(a);
    hi = __uint_as_float(b);
}

// ---------------------------------------------------------------------------
// Per-(dst, relation) in-degree counts.
__global__ void count_kernel(const int* __restrict__ ei, const int* __restrict__ et,
                             int* __restrict__ cnt, int E) {
    int e = blockIdx.x * blockDim.x + threadIdx.x;
    if (e >= E) return;
    atomicAdd(&cnt[ei[E + e] * 3 + et[e]], 1);
}

// inv[i] = 1 / max(cnt[i], 1)
__global__ void inv_kernel(const int* __restrict__ cnt, float* __restrict__ inv, int M) {
    int i = blockIdx.x * blockDim.x + threadIdx.x;
    if (i >= M) return;
    inv[i] = __fdividef(1.0f, (float)max(cnt[i], 1));
}

// Node features: x0 = shape_emb[sid] + col_emb[cid] + pos_emb[pid]  (N x 32)
__global__ void features_kernel(const int* __restrict__ sid, const int* __restrict__ cid,
                                const int* __restrict__ pid,
                                const float* __restrict__ se, const float* __restrict__ ce,
                                const float* __restrict__ pe,
                                float* __restrict__ x0, int N) {
    int t = blockIdx.x * blockDim.x + threadIdx.x;
    int n = t >> 3, q = t & 7;
    if (n >= N) return;
    float4 a = ((const float4*)(se + (size_t)sid[n] * 32))[q];
    float4 b = ((const float4*)(ce + (size_t)cid[n] * 32))[q];
    float4 c = ((const float4*)(pe + (size_t)pid[n] * 32))[q];
    ((float4*)(x0 + (size_t)n * 32))[q] =
        make_float4(a.x + b.x + c.x, a.y + b.y + c.y, a.z + b.z + c.z, a.w + b.w + c.w);
}

// Edge aggregation: agg[dst][et][*] += x[src][*] * inv[dst][et]
// D/4 lanes per edge; one vector RED (red.global.add.v4.f32) per lane.
template <int D>
__global__ void edge_agg_kernel(const float* __restrict__ xin,
                                const int* __restrict__ ei,
                                const int* __restrict__ et,
                                const float* __restrict__ inv,
                                float* __restrict__ agg, int E) {
    constexpr int L = D / 4;
    int t = blockIdx.x * blockDim.x + threadIdx.x;
    int e = t / L, q = t % L;
    if (e >= E) return;
    int s = ei[e], d = ei[E + e], r = et[e];
    int slot = d * 3 + r;
    float w = inv[slot];
    float4 v = ((const float4*)(xin + (size_t)s * D))[q];
    float* o = agg + (size_t)slot * D + q * 4;
    asm volatile("red.global.add.v4.f32 [%0], {%1, %2, %3, %4};"
                 :: "l"(o), "f"(v.x * w), "f"(v.y * w), "f"(v.z * w), "f"(v.w * w)
                 : "memory");
}

// Fused transform: out[n] = act( b + agg[n] (3D wide) @ vstack(W_r) + x[n] @ root )
// = one logical [N x 4D] @ [4D x 64] GEMM on the packed-fp32 (FFMA2) pipe.
//
// Warp-autonomous version: each warp owns 16 nodes and a private smem strip
// (node-major, stride 72 floats -> 4 concurrent scalar LDS hit banks
// {k, k+8, k+16, k+24}: conflict-free). No block barrier in the main loop —
// warps skew into a natural stage/compute software pipeline.
// FFMA2 pairs two adjacent OUTPUTS (weight pairs come free from LDS.128
// register pairs); node value is duplicated with one MOV.
// Per k per thread: 2 LDS.128 + 4 LDS + 4 MOV + 16 FFMA2 (fma-pipe bound).
// Also zeroes `zbuf` (the OTHER layer's agg buffer) for its next use.
template <int D, bool RELU>
__global__ void __launch_bounds__(256)
transform_kernel(const float* __restrict__ agg,
                 const float* __restrict__ xin,
                 const float* __restrict__ W,     // [3*D][64]
                 const float* __restrict__ root,  // [D][64]
                 const float* __restrict__ bias,  // [64]
                 float* __restrict__ out,
                 float* __restrict__ zbuf, int zf4,  // float4s per node to zero
                 int N) {
    constexpr int IN = 4 * D;          // 128 / 256
    constexpr int CH = 64;             // k-chunk staged per pass
    constexpr int NCH = IN / CH;       // 2 / 4
    constexpr int TS = 72;             // floats per staged node row (bank-spread)
    extern __shared__ float smem[];
    float* Ws  = smem;                       // [IN][64] row-major
    float* ins = smem + (size_t)IN * 64;     // [8 warps][16 nodes][TS]

    // Whole block loads weights once.
    for (int i = threadIdx.x; i < IN * 16; i += 256) {
        int k = i >> 4, l = i & 15;
        const float* row = (k < 3 * D) ? (W + (size_t)k * 64) : (root + (size_t)(k - 3 * D) * 64);
        ((float4*)(Ws + (size_t)k * 64))[l] = ((const float4*)row)[l];
    }
    __syncthreads();   // only block-wide barrier

    int w    = threadIdx.x >> 5;
    int lane = threadIdx.x & 31;
    int L    = lane & 7;     // output octet: outputs 8L .. 8L+7 (4 pairs)
    int gN   = lane >> 3;    // node sub-group; thread's nodes: gN + 4p, p=0..3
    float* insw = ins + (size_t)w * 16 * TS;

    float4 bl = ((const float4*)bias)[2 * L];
    float4 bh = ((const float4*)bias)[2 * L + 1];
    unsigned long long binit[4] = {pack2(bl.x, bl.y), pack2(bl.z, bl.w),
                                   pack2(bh.x, bh.y), pack2(bh.z, bh.w)};

    for (int tile = blockIdx.x * 128; tile < N; tile += gridDim.x * 128) {
        int nbase = tile + w * 16;
        unsigned long long acc[4][4];  // [node p][output pair j]
#pragma unroll
        for (int p = 0; p < 4; p++)
#pragma unroll
            for (int j = 0; j < 4; j++) acc[p][j] = binit[j];

#pragma unroll
        for (int c = 0; c < NCH; c++) {
            __syncwarp();   // previous chunk's reads complete before overwrite
            // Stage 16 nodes x 64 k's, node-major (no transpose): 8 float4 per lane.
#pragma unroll
            for (int it = 0; it < 8; it++) {
                int i = lane + 32 * it;
                int nl = i >> 4, kq = i & 15;       // node-local, chunk float4 idx
                int node = nbase + nl;
                float4 v = make_float4(0.f, 0.f, 0.f, 0.f);
                int gq = c * 16 + kq;               // float4 index within node row
                if (node < N) {
                    if (gq < 3 * D / 4) v = ((const float4*)agg)[(size_t)node * (3 * D / 4) + gq];
                    else                v = ((const float4*)xin)[(size_t)node * (D / 4) + gq - 3 * D / 4];
                }
                *(float4*)(insw + (size_t)nl * TS + kq * 4) = v;
            }
            __syncwarp();

            const float* wsc = Ws + (size_t)c * CH * 64;
#pragma unroll 8
            for (int k = 0; k < CH; k++) {
                float4 w0 = *(const float4*)(wsc + (size_t)k * 64 + 8 * L);
                float4 w1 = *(const float4*)(wsc + (size_t)k * 64 + 8 * L + 4);
                unsigned long long wp0 = pack2(w0.x, w0.y);
                unsigned long long wp1 = pack2(w0.z, w0.w);
                unsigned long long wp2 = pack2(w1.x, w1.y);
                unsigned long long wp3 = pack2(w1.z, w1.w);
#pragma unroll
                for (int p = 0; p < 4; p++) {
                    float v = insw[(size_t)(gN + 4 * p) * TS + k];
                    unsigned long long vv = pack2(v, v);
                    ffma2(acc[p][0], vv, wp0);
                    ffma2(acc[p][1], vv, wp1);
                    ffma2(acc[p][2], vv, wp2);
                    ffma2(acc[p][3], vv, wp3);
                }
            }
        }

        // Epilogue: thread writes outputs 8L..8L+7 of its 4 nodes.
#pragma unroll
        for (int p = 0; p < 4; p++) {
            int node = nbase + gN + 4 * p;
            if (node >= N) continue;
            float f[8];
            unpack2(acc[p][0], f[0], f[1]);
            unpack2(acc[p][1], f[2], f[3]);
            unpack2(acc[p][2], f[4], f[5]);
            unpack2(acc[p][3], f[6], f[7]);
            if (RELU) {
#pragma unroll
                for (int q = 0; q < 8; q++) f[q] = fmaxf(f[q], 0.f);
            }
            float4* orow = (float4*)(out + (size_t)node * 64);
            orow[2 * L]     = make_float4(f[0], f[1], f[2], f[3]);
            orow[2 * L + 1] = make_float4(f[4], f[5], f[6], f[7]);
        }

        // Zero-fold: clear the other layer's agg buffer for this node tile.
        {
            const float4 z4 = make_float4(0.f, 0.f, 0.f, 0.f);
            size_t lim = (size_t)N * zf4;
            for (int i = threadIdx.x; i < 128 * zf4; i += 256) {
                size_t idx = (size_t)tile * zf4 + i;
                if (idx < lim) ((float4*)zbuf)[idx] = z4;
            }
        }
    }
}

// Global mean pool (sum + count); 16 lanes per node, vector RED.
__global__ void pool_kernel(const float* __restrict__ h, const int* __restrict__ batch,
                            float* __restrict__ gsum, int* __restrict__ gcnt, int N) {
    int t = blockIdx.x * blockDim.x + threadIdx.x;
    int n = t >> 4, q = t & 15;
    if (n >= N) return;
    int b = batch[n];
    float4 v = ((const float4*)(h + (size_t)n * 64))[q];
    float* o = gsum + (size_t)b * 64 + q * 4;
    asm volatile("red.global.add.v4.f32 [%0], {%1, %2, %3, %4};"
                 :: "l"(o), "f"(v.x), "f"(v.y), "f"(v.z), "f"(v.w)
                 : "memory");
    if (q == 0) atomicAdd(&gcnt[b], 1);
}

// Final: out[g] = (gsum[g]/max(cnt,1)) @ lin_W + lin_b. One warp per graph.
__global__ void pool_final_kernel(const float* __restrict__ gsum, const int* __restrict__ gcnt,
                                  const float* __restrict__ lw, const float* __restrict__ lb,
                                  float* __restrict__ out, int G) {
    int t = blockIdx.x * blockDim.x + threadIdx.x;
    int g = t >> 5, lane = t & 31;
    if (g >= G) return;
    float2 v = ((const float2*)(gsum + (size_t)g * 64))[lane];
    int k0 = 2 * lane, k1 = 2 * lane + 1;
    float a0 = v.x * lw[k0 * 2 + 0] + v.y * lw[k1 * 2 + 0];
    float a1 = v.x * lw[k0 * 2 + 1] + v.y * lw[k1 * 2 + 1];
#pragma unroll
    for (int off = 16; off; off >>= 1) {
        a0 += __shfl_down_sync(0xffffffff, a0, off);
        a1 += __shfl_down_sync(0xffffffff, a1, off);
    }
    if (lane == 0) {
        float c = fmaxf((float)gcnt[g], 1.0f);
        out[g * 2 + 0] = a0 / c + lb[0];
        out[g * 2 + 1] = a1 / c + lb[1];
    }
}

// ---------------------------------------------------------------------------
extern "C" void kernel_launch(void* const* d_in, const int* in_sizes, int n_in,
                              void* d_out, int out_size) {
    const int*   sid   = (const int*)d_in[0];
    const int*   cid   = (const int*)d_in[1];
    const int*   pid   = (const int*)d_in[2];
    const int*   ei    = (const int*)d_in[3];   // [2, E]: row0 = src, row1 = dst
    const int*   et    = (const int*)d_in[4];
    const int*   batch = (const int*)d_in[5];
    // d_in[6] = num_graphs (scalar), unused
    const float* se = (const float*)d_in[7];
    const float* ce = (const float*)d_in[8];
    const float* pe = (const float*)d_in[9];
    const float* W1 = (const float*)d_in[10];
    const float* r1 = (const float*)d_in[11];
    const float* b1 = (const float*)d_in[12];
    const float* W2 = (const float*)d_in[13];
    const float* r2 = (const float*)d_in[14];
    const float* b2 = (const float*)d_in[15];
    const float* lw = (const float*)d_in[16];
    const float* lb = (const float*)d_in[17];
    float* out = (float*)d_out;

    const int N = in_sizes[0];
    const int E = in_sizes[4];
    const int G = out_size / 2;

    void *p_x0, *p_h1, *p_h2, *p_agg1, *p_agg2, *p_cnt, *p_inv, *p_gsum, *p_gcnt;
    cudaGetSymbolAddress(&p_x0, g_x0);
    cudaGetSymbolAddress(&p_h1, g_h1);
    cudaGetSymbolAddress(&p_h2, g_h2);
    cudaGetSymbolAddress(&p_agg1, g_agg1);
    cudaGetSymbolAddress(&p_agg2, g_agg2);
    cudaGetSymbolAddress(&p_cnt, g_cnt);
    cudaGetSymbolAddress(&p_inv, g_inv);
    cudaGetSymbolAddress(&p_gsum, g_gsum);
    cudaGetSymbolAddress(&p_gcnt, g_gcnt);

    // smem: layer1 = 128*64*4 + 8*16*72*4 = 69632 B (3 blocks/SM)
    //       layer2 = 256*64*4 + 8*16*72*4 = 102400 B (2 blocks/SM)
    cudaFuncSetAttribute(transform_kernel<32, true>,
                         cudaFuncAttributeMaxDynamicSharedMemorySize, 70 * 1024);
    cudaFuncSetAttribute(transform_kernel<64, true>,
                         cudaFuncAttributeMaxDynamicSharedMemorySize, 102 * 1024);

    cudaMemsetAsync(p_cnt, 0, (size_t)N * 3 * sizeof(int));
    cudaMemsetAsync(p_gsum, 0, (size_t)G * 64 * sizeof(float));
    cudaMemsetAsync(p_gcnt, 0, (size_t)G * sizeof(int));

    count_kernel<<<(E + 255) / 256, 256>>>(ei, et, (int*)p_cnt, E);
    inv_kernel<<<(N * 3 + 255) / 256, 256>>>((const int*)p_cnt, (float*)p_inv, N * 3);
    features_kernel<<<(N * 8 + 255) / 256, 256>>>(sid, cid, pid, se, ce, pe, (float*)p_x0, N);

    // ---- Layer 1 (D = 32) ----
    // agg1 was zeroed by the previous call's transform<64> (or load-time init).
    edge_agg_kernel<32><<<(E * 8 + 255) / 256, 256>>>(
        (const float*)p_x0, ei, et, (const float*)p_inv, (float*)p_agg1, E);
    {
        int smem1 = (128 * 64 + 8 * 16 * 72) * (int)sizeof(float);  // 69632 B
        transform_kernel<32, true><<<444, 256, smem1>>>(
            (const float*)p_agg1, (const float*)p_x0, W1, r1, b1, (float*)p_h1,
            (float*)p_agg2, 3 * 64 / 4, N);   // zero agg2 for layer 2
    }

    // ---- Layer 2 (D = 64) ----
    edge_agg_kernel<64><<<(E * 16 + 255) / 256, 256>>>(
        (const float*)p_h1, ei, et, (const float*)p_inv, (float*)p_agg2, E);
    {
        int smem2 = (256 * 64 + 8 * 16 * 72) * (int)sizeof(float);  // 102400 B
        transform_kernel<64, true><<<296, 256, smem2>>>(
            (const float*)p_agg2, (const float*)p_h1, W2, r2, b2, (float*)p_h2,
            (float*)p_agg1, 3 * 32 / 4, N);   // zero agg1 for the next call
    }

    // ---- Pool + head ----
    pool_kernel<<<(N * 16 + 255) / 256, 256>>>(
        (const float*)p_h2, batch, (float*)p_gsum, (int*)p_gcnt, N);
    pool_final_kernel<<<(G * 32 + 255) / 256, 256>>>(
        (const float*)p_gsum, (const int*)p_gcnt, lw, lb, out, G);
}